// round 15
// baseline (speedup 1.0000x reference)
#include <cuda_runtime.h>
#include <cuda_fp16.h>
#include <math.h>
#include <stdint.h>

#define N 100000
#define E 400000
#define HID 128
#define NH 8

// ---------------- device scratch ----------------
__device__ __align__(16) uint32_t g_h16[2][(size_t)N * 64];  // fp16x2 projected features
__device__ __align__(16) float g_alphaS[4][(size_t)N * NH];  // [n*8 + h]
__device__ __align__(16) float g_alphaD[4][(size_t)N * NH];
__device__ int   g_deg[4][N];
__device__ int   g_rowptr[4][N + 1];
__device__ int   g_bsum[4][128];
__device__ int   g_boff[4][128];
__device__ int   g_srcs[4][E];
__device__ __align__(16) uint32_t g_of[4][(size_t)N * 64];   // fp16x2 o (single copy)
__device__ float g_score[4];
__device__ float g_attn[4];
__device__ float g_st[2][5][HID];   // s0,s1,ss0,ss1,cross per type per column
__device__ float g_scale[2][HID];
__device__ float g_shift[2][HID];
// W as pre-packed f16 MMA B-fragments: [which][((whalf*8+nt)*8+kc)*32+lane] = {b0,b1}
__device__ __align__(16) uint2 g_Wfrag[3][4096];

// ---------------- helpers ----------------
__device__ __forceinline__ uint32_t pack_h2(float x, float y) {
    __half2 p = __floats2half2_rn(x, y);
    return *reinterpret_cast<uint32_t*>(&p);
}

__device__ __forceinline__ void unpack_h2(uint32_t u, float& a, float& b) {
    __half2 p = *reinterpret_cast<__half2*>(&u);
    a = __low2float(p);
    b = __high2float(p);
}

// exact hi/lo split of fp32 pair into two f16 pairs
__device__ __forceinline__ void split2h(float x, float y, uint32_t& hi, uint32_t& lo) {
    __half hx = __float2half_rn(x), hy = __float2half_rn(y);
    __half2 hp(hx, hy);
    hi = *reinterpret_cast<uint32_t*>(&hp);
    lo = pack_h2(x - __half2float(hx), y - __half2float(hy));
}

__device__ __forceinline__ void mma_f16(float* d, const uint32_t* a, uint32_t b0, uint32_t b1) {
    asm volatile(
        "mma.sync.aligned.m16n8k16.row.col.f32.f16.f16.f32 "
        "{%0,%1,%2,%3}, {%4,%5,%6,%7}, {%8,%9}, {%0,%1,%2,%3};"
        : "+f"(d[0]), "+f"(d[1]), "+f"(d[2]), "+f"(d[3])
        : "r"(a[0]), "r"(a[1]), "r"(a[2]), "r"(a[3]), "r"(b0), "r"(b1));
}

__device__ __forceinline__ void ldsm4(uint32_t* r, uint32_t addr) {
    asm volatile("ldmatrix.sync.aligned.m8n8.x4.shared.b16 {%0,%1,%2,%3}, [%4];"
        : "=r"(r[0]), "=r"(r[1]), "=r"(r[2]), "=r"(r[3]) : "r"(addr));
}

__device__ __forceinline__ uint32_t smem_u32(const void* p) {
    uint32_t a;
    asm("{ .reg .u64 t; cvta.to.shared.u64 t, %1; cvt.u32.u64 %0, t; }" : "=r"(a) : "l"(p));
    return a;
}

// stage a 128-row x 64-u32 tile (pitch 68 u32) from global via cp.async, 16B chunks
__device__ __forceinline__ void stage_tile(uint32_t sbase_bytes, const uint32_t* __restrict__ src,
                                           int row0, int arows) {
    int t = threadIdx.x;
#pragma unroll
    for (int i = 0; i < 8; i++) {
        int idx = i * 256 + t;            // [0, 2048)
        int r = idx >> 4, c = idx & 15;
        int gr = row0 + r;
        bool ok = (gr < arows);
        const uint32_t* s = src + (size_t)(ok ? gr : 0) * 64 + c * 4;
        uint32_t dst = sbase_bytes + (r * 68 + c * 4) * 4;
        int sz = ok ? 16 : 0;
        asm volatile("cp.async.cg.shared.global [%0], [%1], 16, %2;" :: "r"(dst), "l"(s), "r"(sz));
    }
}

#define CP_COMMIT_WAIT() do { \
    asm volatile("cp.async.commit_group;" ::: "memory"); \
    asm volatile("cp.async.wait_group 0;" ::: "memory"); \
} while (0)

// ---------------- f16 GEMM compute on staged A tiles + global W fragments ----------------
template <int NPASS>
__device__ __forceinline__ void gemm_compute(uint32_t sb, const int* AO,
                                             const uint2* __restrict__ Wf, float* acc) {
    int t = threadIdx.x;
    int wid = t >> 5, lane = t & 31;
    int wr = (wid >> 1) * 32, whalf = wid & 1;
    int g = lane >> 3;
    int rowoff = (g & 1) * 8 + (lane & 7);
    int koff = (g >> 1) * 16;

#pragma unroll
    for (int i = 0; i < 64; i++) acc[i] = 0.f;

#pragma unroll
    for (int p = 0; p < NPASS; p++) {
        uint32_t abase = sb + (uint32_t)(AO[p] + (wr + rowoff) * 68) * 4 + koff;
        const uint2* Wb = Wf + whalf * 2048 + lane;
#pragma unroll 2
        for (int kc = 0; kc < 8; kc++) {
            uint32_t a0[4], a1[4];
            ldsm4(a0, abase + kc * 32);
            ldsm4(a1, abase + kc * 32 + 16 * 68 * 4);
#pragma unroll
            for (int nt = 0; nt < 8; nt++) {
                uint2 b = __ldg(&Wb[(nt * 8 + kc) * 32]);
                mma_f16(acc + (0 * 8 + nt) * 4, a0, b.x, b.y);
                mma_f16(acc + (1 * 8 + nt) * 4, a1, b.x, b.y);
            }
        }
    }
}

// ---------------- weight prep: pack f16 MMA B fragments ----------------
__global__ void prep_w_kernel(const float* __restrict__ W_a,
                              const float* __restrict__ W_b,
                              const float* __restrict__ Wk) {
    int which = blockIdx.x;
    const float* W = which == 0 ? W_a : (which == 1 ? W_b : Wk);
    for (int i = threadIdx.x; i < 4096; i += blockDim.x) {
        int lane = i & 31;
        int kc = (i >> 5) & 7;
        int nt = (i >> 8) & 7;
        int whalf = (i >> 11) & 1;
        int n = whalf * 64 + nt * 8 + (lane >> 2);
        int kw0 = kc * 8 + (lane & 3);
        int kw1 = kw0 + 4;
        float x0 = W[(2 * kw0) * 128 + n], x1 = W[(2 * kw0 + 1) * 128 + n];
        float y0 = W[(2 * kw1) * 128 + n], y1 = W[(2 * kw1 + 1) * 128 + n];
        g_Wfrag[which][i] = make_uint2(pack_h2(x0, x1), pack_h2(y0, y1));
    }
}

// smem u32-index layout (proj): AH, AL pitch-68 tiles + satt
#define SW_AH 0
#define SW_AL 8704
#define SW_SATT 17408
#define PROJ_SMEM_BYTES ((17408 + 512) * 4)

// sem layout: AH + red
#define SEM_RED 8704
#define SEM_SMEM_BYTES ((8704 + 64) * 4)

// ---------------- projection (both types, blockIdx.y = type), 2-pass f16 ----------------
__global__ void __launch_bounds__(256, 2) proj_mma_kernel(
    const float* __restrict__ x_a, const float* __restrict__ x_b,
    const float* __restrict__ b_a, const float* __restrict__ b_b,
    const float* __restrict__ atA0, const float* __restrict__ atA1,
    const float* __restrict__ atA2, const float* __restrict__ atA3,
    const float* __restrict__ atB0, const float* __restrict__ atB1,
    const float* __restrict__ atB2, const float* __restrict__ atB3) {
    extern __shared__ uint32_t smemu[];
    float* smemf = (float*)smemu;
    float* satt = smemf + SW_SATT;
    uint32_t sb = smem_u32(smemu);

    int type = blockIdx.y;
    const float* X = type == 0 ? x_a : x_b;
    const float* bias = type == 0 ? b_a : b_b;

    int t = threadIdx.x;
    for (int i = t; i < 512; i += 256) {
        int arr = i >> 7, col = i & 127;
        const float* p;
        if (type == 0)
            p = arr == 0 ? atA0 : arr == 1 ? atA1 : arr == 2 ? atA2 : atA3;
        else
            p = arr == 0 ? atB0 : arr == 1 ? atB1 : arr == 2 ? atB2 : atB3;
        satt[i] = __ldg(&p[col]);
    }

    int row0 = blockIdx.x * 128;
    const float4* X4 = (const float4*)X;
#pragma unroll
    for (int i = 0; i < 16; i++) {
        int idx = i * 256 + t;
        int r = idx >> 5, c4 = idx & 31;
        int gr = row0 + r;
        float4 v = make_float4(0.f, 0.f, 0.f, 0.f);
        if (gr < N) v = X4[(size_t)gr * 32 + c4];
        uint32_t h0, l0, h1, l1;
        split2h(v.x, v.y, h0, l0);
        split2h(v.z, v.w, h1, l1);
        int base = r * 68 + c4 * 2;
        smemu[SW_AH + base] = h0;
        smemu[SW_AH + base + 1] = h1;
        smemu[SW_AL + base] = l0;
        smemu[SW_AL + base + 1] = l1;
    }
    __syncthreads();

    float acc[64];
    const int AO[2] = {SW_AH, SW_AL};
    gemm_compute<2>(sb, AO, g_Wfrag[type], acc);

    uint32_t* Hout = g_h16[type];
    int rS0 = type == 0 ? 0 : 1, rS1 = type == 0 ? 2 : 3;
    int rD0 = type == 0 ? 1 : 0, rD1 = type == 0 ? 2 : 3;

    int wid = t >> 5, lane = t & 31;
    int wr = (wid >> 1) * 32, wc = (wid & 1) * 64;

    __syncthreads();  // done reading A smem; reuse as vbuf (pitch 134 floats)

#pragma unroll
    for (int rt = 0; rt < 2; rt++) {
#pragma unroll
        for (int hr = 0; hr < 2; hr++) {
            int lrow = wr + rt * 16 + hr * 8 + (lane >> 2);
            int grow = row0 + lrow;
#pragma unroll
            for (int nt = 0; nt < 8; nt++) {
                int col = wc + nt * 8 + (lane & 3) * 2;
                float2 bb = __ldg((const float2*)(bias + col));
                float v0 = acc[(rt * 8 + nt) * 4 + hr * 2] + bb.x;
                float v1 = acc[(rt * 8 + nt) * 4 + hr * 2 + 1] + bb.y;
                if (grow < N)
                    Hout[(size_t)grow * 64 + (col >> 1)] = pack_h2(v0, v1);
                *(float2*)(smemf + lrow * 134 + col) = make_float2(v0, v1);
            }
        }
    }
    __syncthreads();

    if (t < 128) {
        int node = row0 + t;
        if (node < N) {
            const float* vrow = smemf + t * 134;
            float* aS0 = &g_alphaS[rS0][0];
            float* aS1 = &g_alphaS[rS1][0];
            float* aD0 = &g_alphaD[rD0][0];
            float* aD1 = &g_alphaD[rD1][0];
#pragma unroll
            for (int h = 0; h < 8; h++) {
                float p0 = 0.f, p1 = 0.f, p2 = 0.f, p3 = 0.f;
#pragma unroll
                for (int i = 0; i < 16; i++) {
                    int col = h * 16 + i;
                    float v = vrow[col];
                    p0 = fmaf(v, satt[0 * 128 + col], p0);
                    p1 = fmaf(v, satt[1 * 128 + col], p1);
                    p2 = fmaf(v, satt[2 * 128 + col], p2);
                    p3 = fmaf(v, satt[3 * 128 + col], p3);
                }
                aS0[node * 8 + h] = p0;
                aS1[node * 8 + h] = p1;
                aD0[node * 8 + h] = p2;
                aD1[node * 8 + h] = p3;
            }
        }
    }
}

// ---------------- semantic score (blockIdx.y = rel), single-pass f16 ----------------
__global__ void __launch_bounds__(256, 2) sem_mma_kernel(
    const float* __restrict__ bk, const float* __restrict__ q) {
    extern __shared__ uint32_t smemu[];
    float* red = (float*)smemu + SEM_RED;
    uint32_t sb = smem_u32(smemu);
    int rel = blockIdx.y;
    int row0 = blockIdx.x * 128;

    stage_tile(sb, g_of[rel], row0, N);
    CP_COMMIT_WAIT();
    __syncthreads();

    float acc[64];
    const int AO[1] = {0};
    gemm_compute<1>(sb, AO, g_Wfrag[2], acc);

    int t = threadIdx.x;
    int wid = t >> 5, lane = t & 31;
    int wr = (wid >> 1) * 32, wc = (wid & 1) * 64;

    float local = 0.f;
#pragma unroll
    for (int rt = 0; rt < 2; rt++) {
#pragma unroll
        for (int hr = 0; hr < 2; hr++) {
            int grow = row0 + wr + rt * 16 + hr * 8 + (lane >> 2);
            if (grow < N) {
#pragma unroll
                for (int nt = 0; nt < 8; nt++) {
                    int col = wc + nt * 8 + (lane & 3) * 2;
                    float2 bb = __ldg((const float2*)(bk + col));
                    float2 qq = __ldg((const float2*)(q + col));
                    float v0 = acc[(rt * 8 + nt) * 4 + hr * 2] + bb.x;
                    float v1 = acc[(rt * 8 + nt) * 4 + hr * 2 + 1] + bb.y;
                    local += tanhf(v0) * qq.x + tanhf(v1) * qq.y;
                }
            }
        }
    }
#pragma unroll
    for (int off = 16; off >= 1; off >>= 1)
        local += __shfl_down_sync(0xffffffff, local, off);
    __syncthreads();
    if (lane == 0) red[wid] = local;
    __syncthreads();
    if (t == 0) {
        float s = 0.f;
#pragma unroll
        for (int w = 0; w < 8; w++) s += red[w];
        atomicAdd(&g_score[rel], s);
    }
}

// ---------------- init ----------------
__global__ void init_kernel() {
    int i = blockIdx.x * blockDim.x + threadIdx.x;
    int stride = gridDim.x * blockDim.x;
    int* degf = &g_deg[0][0];
    for (int k = i; k < 4 * N; k += stride) degf[k] = 0;
    if (i < 4) g_score[i] = 0.f;
    if (i < 2 * 5 * HID) (&g_st[0][0][0])[i] = 0.f;
}

// ---------------- CSR build ----------------
__global__ void count_kernel(const int* __restrict__ e0, const int* __restrict__ e1,
                             const int* __restrict__ e2, const int* __restrict__ e3) {
    int rel = blockIdx.y;
    const int* ei = rel == 0 ? e0 : rel == 1 ? e1 : rel == 2 ? e2 : e3;
    int e = blockIdx.x * blockDim.x + threadIdx.x;
    if (e < E) atomicAdd(&g_deg[rel][ei[E + e]], 1);
}

__global__ void scan1_kernel() {
    int rel = blockIdx.y;
    int i = blockIdx.x * 1024 + threadIdx.x;
    int lane = threadIdx.x & 31, wid = threadIdx.x >> 5;
    int v = (i < N) ? g_deg[rel][i] : 0;
    int x = v;
#pragma unroll
    for (int o = 1; o < 32; o <<= 1) {
        int y = __shfl_up_sync(0xffffffff, x, o);
        if (lane >= o) x += y;
    }
    __shared__ int ws[32];
    if (lane == 31) ws[wid] = x;
    __syncthreads();
    if (wid == 0) {
        int s = ws[lane];
#pragma unroll
        for (int o = 1; o < 32; o <<= 1) {
            int y = __shfl_up_sync(0xffffffff, s, o);
            if (lane >= o) s += y;
        }
        ws[lane] = s;
    }
    __syncthreads();
    int incl = x + (wid ? ws[wid - 1] : 0);
    if (i < N) g_rowptr[rel][i] = incl - v;
    if (threadIdx.x == 1023) g_bsum[rel][blockIdx.x] = incl;
}

__global__ void scan2_kernel() {
    int rel = blockIdx.x;
    int t = threadIdx.x;  // 128
    int lane = t & 31, wid = t >> 5;
    int v = (t < 98) ? g_bsum[rel][t] : 0;
    int x = v;
#pragma unroll
    for (int o = 1; o < 32; o <<= 1) {
        int y = __shfl_up_sync(0xffffffff, x, o);
        if (lane >= o) x += y;
    }
    __shared__ int ws[4];
    if (lane == 31) ws[wid] = x;
    __syncthreads();
    int prefix = 0;
    for (int k = 0; k < wid; k++) prefix += ws[k];
    int incl = x + prefix;
    if (t < 98) g_boff[rel][t] = incl - v;
    if (t == 0) g_rowptr[rel][N] = E;
}

__global__ void scan3_kernel() {
    int rel = blockIdx.y;
    int i = blockIdx.x * 1024 + threadIdx.x;
    if (i < N) {
        g_rowptr[rel][i] += g_boff[rel][blockIdx.x];
        g_deg[rel][i] = 0;  // reset cursor for scatter
    }
}

__global__ void scatter_kernel(const int* __restrict__ e0, const int* __restrict__ e1,
                               const int* __restrict__ e2, const int* __restrict__ e3) {
    int rel = blockIdx.y;
    const int* ei = rel == 0 ? e0 : rel == 1 ? e1 : rel == 2 ? e2 : e3;
    int e = blockIdx.x * blockDim.x + threadIdx.x;
    if (e < E) {
        int s = ei[e], d = ei[E + e];
        int pos = g_rowptr[rel][d] + atomicAdd(&g_deg[rel][d], 1);
        g_srcs[rel][pos] = s;
    }
}

// ---------------- aggregate: two nodes/warp, 4-edge unroll ----------------
__global__ void aggregate_kernel() {
    int rel = blockIdx.y;
    const uint32_t* hs = g_h16[(rel == 0 || rel == 2) ? 0 : 1];
    int w = (blockIdx.x * blockDim.x + threadIdx.x) >> 5;
    int lane = threadIdx.x & 31;
    int n = w * 2 + (lane >> 4);
    if (n >= N) return;
    int sl = lane & 15;       // sublane: dims [sl*8, sl*8+8)
    int h = sl >> 1;

    const float* aS = g_alphaS[rel];
    float ad = g_alphaD[rel][n * 8 + h];
    int beg = g_rowptr[rel][n], end = g_rowptr[rel][n + 1];
    const int* srcs = g_srcs[rel];

    float den = 0.f;
    float av[8];
#pragma unroll
    for (int i = 0; i < 8; i++) av[i] = 0.f;

    int e = beg;
    for (; e + 4 <= end; e += 4) {
        int s0 = __ldg(&srcs[e]), s1 = __ldg(&srcs[e + 1]);
        int s2 = __ldg(&srcs[e + 2]), s3 = __ldg(&srcs[e + 3]);
        float a0 = __ldg(&aS[s0 * 8 + h]) + ad;
        float a1 = __ldg(&aS[s1 * 8 + h]) + ad;
        float a2 = __ldg(&aS[s2 * 8 + h]) + ad;
        float a3 = __ldg(&aS[s3 * 8 + h]) + ad;
        a0 = a0 > 0.f ? a0 : 0.2f * a0;
        a1 = a1 > 0.f ? a1 : 0.2f * a1;
        a2 = a2 > 0.f ? a2 : 0.2f * a2;
        a3 = a3 > 0.f ? a3 : 0.2f * a3;
        float w0 = __expf(a0), w1 = __expf(a1), w2 = __expf(a2), w3 = __expf(a3);
        den += (w0 + w1) + (w2 + w3);
        uint4 u0 = *reinterpret_cast<const uint4*>(hs + (size_t)s0 * 64 + sl * 4);
        uint4 u1 = *reinterpret_cast<const uint4*>(hs + (size_t)s1 * 64 + sl * 4);
        uint4 u2 = *reinterpret_cast<const uint4*>(hs + (size_t)s2 * 64 + sl * 4);
        uint4 u3 = *reinterpret_cast<const uint4*>(hs + (size_t)s3 * 64 + sl * 4);
        float f0[8], f1[8], f2[8], f3[8];
        unpack_h2(u0.x, f0[0], f0[1]); unpack_h2(u0.y, f0[2], f0[3]);
        unpack_h2(u0.z, f0[4], f0[5]); unpack_h2(u0.w, f0[6], f0[7]);
        unpack_h2(u1.x, f1[0], f1[1]); unpack_h2(u1.y, f1[2], f1[3]);
        unpack_h2(u1.z, f1[4], f1[5]); unpack_h2(u1.w, f1[6], f1[7]);
        unpack_h2(u2.x, f2[0], f2[1]); unpack_h2(u2.y, f2[2], f2[3]);
        unpack_h2(u2.z, f2[4], f2[5]); unpack_h2(u2.w, f2[6], f2[7]);
        unpack_h2(u3.x, f3[0], f3[1]); unpack_h2(u3.y, f3[2], f3[3]);
        unpack_h2(u3.z, f3[4], f3[5]); unpack_h2(u3.w, f3[6], f3[7]);
#pragma unroll
        for (int i = 0; i < 8; i++)
            av[i] = fmaf(w0, f0[i], fmaf(w1, f1[i], fmaf(w2, f2[i], fmaf(w3, f3[i], av[i]))));
    }
    if (e + 2 <= end) {
        int s0 = __ldg(&srcs[e]), s1 = __ldg(&srcs[e + 1]);
        float a0 = __ldg(&aS[s0 * 8 + h]) + ad;
        float a1 = __ldg(&aS[s1 * 8 + h]) + ad;
        a0 = a0 > 0.f ? a0 : 0.2f * a0;
        a1 = a1 > 0.f ? a1 : 0.2f * a1;
        float w0 = __expf(a0), w1 = __expf(a1);
        den += w0 + w1;
        uint4 u0 = *reinterpret_cast<const uint4*>(hs + (size_t)s0 * 64 + sl * 4);
        uint4 u1 = *reinterpret_cast<const uint4*>(hs + (size_t)s1 * 64 + sl * 4);
        float f0[8], f1[8];
        unpack_h2(u0.x, f0[0], f0[1]); unpack_h2(u0.y, f0[2], f0[3]);
        unpack_h2(u0.z, f0[4], f0[5]); unpack_h2(u0.w, f0[6], f0[7]);
        unpack_h2(u1.x, f1[0], f1[1]); unpack_h2(u1.y, f1[2], f1[3]);
        unpack_h2(u1.z, f1[4], f1[5]); unpack_h2(u1.w, f1[6], f1[7]);
#pragma unroll
        for (int i = 0; i < 8; i++)
            av[i] = fmaf(w0, f0[i], fmaf(w1, f1[i], av[i]));
        e += 2;
    }
    if (e < end) {
        int s0 = __ldg(&srcs[e]);
        float a0 = __ldg(&aS[s0 * 8 + h]) + ad;
        a0 = a0 > 0.f ? a0 : 0.2f * a0;
        float w0 = __expf(a0);
        den += w0;
        uint4 u0 = *reinterpret_cast<const uint4*>(hs + (size_t)s0 * 64 + sl * 4);
        float f0[8];
        unpack_h2(u0.x, f0[0], f0[1]); unpack_h2(u0.y, f0[2], f0[3]);
        unpack_h2(u0.z, f0[4], f0[5]); unpack_h2(u0.w, f0[6], f0[7]);
#pragma unroll
        for (int i = 0; i < 8; i++)
            av[i] = fmaf(w0, f0[i], av[i]);
    }
    float inv = 1.f / (den + 1e-16f);
    uint4 o;
    o.x = pack_h2(fmaxf(av[0] * inv, 0.f), fmaxf(av[1] * inv, 0.f));
    o.y = pack_h2(fmaxf(av[2] * inv, 0.f), fmaxf(av[3] * inv, 0.f));
    o.z = pack_h2(fmaxf(av[4] * inv, 0.f), fmaxf(av[5] * inv, 0.f));
    o.w = pack_h2(fmaxf(av[6] * inv, 0.f), fmaxf(av[7] * inv, 0.f));
    *reinterpret_cast<uint4*>(&g_of[rel][(size_t)n * 64 + sl * 4]) = o;
}

// ---------------- BN stats from fp16 o (5 stats per type per column) ----------------
__global__ void stats_kernel() {
    int type = blockIdx.y;
    int rel0 = type == 0 ? 1 : 0;
    int rel1 = type == 0 ? 2 : 3;
    int t = threadIdx.x;        // 256
    int cp = t & 63, rg = t >> 6;
    int r0 = blockIdx.x * 512;
    int rend = r0 + 512;
    if (rend > N) rend = N;

    float s0a = 0.f, s1a = 0.f, ss0a = 0.f, ss1a = 0.f, cxa = 0.f;
    float s0b = 0.f, s1b = 0.f, ss0b = 0.f, ss1b = 0.f, cxb = 0.f;
    for (int r = r0 + rg; r < rend; r += 4) {
        uint32_t u0 = g_of[rel0][(size_t)r * 64 + cp];
        uint32_t u1 = g_of[rel1][(size_t)r * 64 + cp];
        float xa, xb, ya, yb;
        unpack_h2(u0, xa, xb);
        unpack_h2(u1, ya, yb);
        s0a += xa; s1a += ya; ss0a += xa * xa; ss1a += ya * ya; cxa += xa * ya;
        s0b += xb; s1b += yb; ss0b += xb * xb; ss1b += yb * yb; cxb += xb * yb;
    }
    __shared__ float red[4][64][10];
    float* my = red[rg][cp];
    my[0] = s0a; my[1] = s1a; my[2] = ss0a; my[3] = ss1a; my[4] = cxa;
    my[5] = s0b; my[6] = s1b; my[7] = ss0b; my[8] = ss1b; my[9] = cxb;
    __syncthreads();
    if (rg == 0) {
#pragma unroll
        for (int k = 0; k < 10; k++) {
            float v = red[0][cp][k] + red[1][cp][k] + red[2][cp][k] + red[3][cp][k];
            int stat = k % 5;
            int col = cp * 2 + (k / 5);
            atomicAdd(&g_st[type][stat][col], v);
        }
    }
}

// ---------------- BN params (computes semantic attn inline) ----------------
__global__ void bnparam_kernel(const float* __restrict__ gamma,
                               const float* __restrict__ beta) {
    int t = threadIdx.x;  // 256
    int type = t >> 7, j = t & 127;
    int r0 = type == 0 ? 1 : 0, r1 = type == 0 ? 2 : 3;
    float sc0 = g_score[r0] / (float)N, sc1 = g_score[r1] / (float)N;
    float m = fmaxf(sc0, sc1);
    float e0 = expf(sc0 - m), e1 = expf(sc1 - m);
    float a0 = e0 / (e0 + e1), a1 = e1 / (e0 + e1);
    if (j == 0) {
        g_attn[type * 2 + 0] = a0;
        g_attn[type * 2 + 1] = a1;
    }
    float s0 = g_st[type][0][j], s1 = g_st[type][1][j];
    float ss0 = g_st[type][2][j], ss1 = g_st[type][3][j], cx = g_st[type][4][j];
    float mu = (a0 * s0 + a1 * s1) / (float)N;
    float ex2 = (a0 * a0 * ss0 + 2.f * a0 * a1 * cx + a1 * a1 * ss1) / (float)N;
    float var = ex2 - mu * mu;
    float rstd = rsqrtf(var + 1e-5f);
    float sc = rstd * gamma[j];
    g_scale[type][j] = sc;
    g_shift[type][j] = beta[j] - mu * sc;
}

// ---------------- fused combine + normalize (reads fp16 o) ----------------
__global__ void combine_norm_kernel(float* __restrict__ out) {
    int stride = gridDim.x * blockDim.x;
    int total = 2 * N * 32;  // uint2 (4 cols) units
    for (int i = blockIdx.x * blockDim.x + threadIdx.x; i < total; i += stride) {
        int type = (i >= N * 32) ? 1 : 0;
        int local = i - type * N * 32;
        const uint2* o0 = (const uint2*)(type == 0 ? g_of[1] : g_of[0]);
        const uint2* o1 = (const uint2*)(type == 0 ? g_of[2] : g_of[3]);
        float a0 = g_attn[type * 2 + 0], a1 = g_attn[type * 2 + 1];
        uint2 u0 = o0[local], u1 = o1[local];
        float x0, x1, x2, x3, y0, y1, y2, y3;
        unpack_h2(u0.x, x0, x1);
        unpack_h2(u0.y, x2, x3);
        unpack_h2(u1.x, y0, y1);
        unpack_h2(u1.y, y2, y3);
        int j = (local & 31) * 4;
        const float* sc = g_scale[type];
        const float* sf = g_shift[type];
        float4 r;
        r.x = (a0 * x0 + a1 * y0) * sc[j + 0] + sf[j + 0];
        r.y = (a0 * x1 + a1 * y1) * sc[j + 1] + sf[j + 1];
        r.z = (a0 * x2 + a1 * y2) * sc[j + 2] + sf[j + 2];
        r.w = (a0 * x3 + a1 * y3) * sc[j + 3] + sf[j + 3];
        ((float4*)out)[i] = r;
    }
}

// ---------------- host ----------------
static cudaStream_t g_s2 = 0;
static cudaEvent_t g_evA, g_evB, g_evC, g_evD;

extern "C" void kernel_launch(void* const* d_in, const int* in_sizes, int n_in,
                              void* d_out, int out_size) {
    const float* x_a = (const float*)d_in[0];
    const float* x_b = (const float*)d_in[1];
    const int* ei_ab = (const int*)d_in[2];
    const int* ei_ba = (const int*)d_in[3];
    const int* ei_aa = (const int*)d_in[4];
    const int* ei_bb = (const int*)d_in[5];
    const float* W_a = (const float*)d_in[6];
    const float* b_a = (const float*)d_in[7];
    const float* W_b = (const float*)d_in[8];
    const float* b_b = (const float*)d_in[9];
    const float* att_ab_s = (const float*)d_in[10];
    const float* att_ab_d = (const float*)d_in[11];
    const float* att_ba_s = (const float*)d_in[12];
    const float* att_ba_d = (const float*)d_in[13];
    const float* att_aa_s = (const float*)d_in[14];
    const float* att_aa_d = (const float*)d_in[15];
    const float* att_bb_s = (const float*)d_in[16];
    const float* att_bb_d = (const float*)d_in[17];
    const float* Wk = (const float*)d_in[18];
    const float* bk = (const float*)d_in[19];
    const float* q  = (const float*)d_in[20];
    const float* gamma = (const float*)d_in[21];
    const float* beta  = (const float*)d_in[22];
    float* out = (float*)d_out;

    if (g_s2 == 0) {
        cudaStreamCreateWithFlags(&g_s2, cudaStreamNonBlocking);
        cudaEventCreateWithFlags(&g_evA, cudaEventDisableTiming);
        cudaEventCreateWithFlags(&g_evB, cudaEventDisableTiming);
        cudaEventCreateWithFlags(&g_evC, cudaEventDisableTiming);
        cudaEventCreateWithFlags(&g_evD, cudaEventDisableTiming);
        cudaFuncSetAttribute(proj_mma_kernel, cudaFuncAttributeMaxDynamicSharedMemorySize, PROJ_SMEM_BYTES);
        cudaFuncSetAttribute(sem_mma_kernel, cudaFuncAttributeMaxDynamicSharedMemorySize, SEM_SMEM_BYTES);
    }

    init_kernel<<<512, 256>>>();

    // fork: CSR chain on side stream, overlapped with projection GEMMs
    cudaEventRecord(g_evA, 0);
    cudaStreamWaitEvent(g_s2, g_evA, 0);

    prep_w_kernel<<<3, 256>>>(W_a, W_b, Wk);

    int mmGrid = (N + 127) / 128;  // 782
    dim3 pGrid(mmGrid, 2);
    proj_mma_kernel<<<pGrid, 256, PROJ_SMEM_BYTES>>>(
        x_a, x_b, b_a, b_b,
        att_ab_s, att_aa_s, att_ba_d, att_aa_d,
        att_ba_s, att_bb_s, att_ab_d, att_bb_d);

    dim3 eGrid((E + 255) / 256, 4);
    dim3 sGrid((N + 1023) / 1024, 4);
    count_kernel<<<eGrid, 256, 0, g_s2>>>(ei_ab, ei_ba, ei_aa, ei_bb);
    scan1_kernel<<<sGrid, 1024, 0, g_s2>>>();
    scan2_kernel<<<4, 128, 0, g_s2>>>();
    scan3_kernel<<<sGrid, 1024, 0, g_s2>>>();
    scatter_kernel<<<eGrid, 256, 0, g_s2>>>(ei_ab, ei_ba, ei_aa, ei_bb);

    // join: aggregate needs alphas (stream 0) + CSR (s2)
    cudaEventRecord(g_evB, g_s2);
    cudaStreamWaitEvent(0, g_evB, 0);

    dim3 aggGrid(((N + 1) / 2 * 32 + 255) / 256, 4);
    aggregate_kernel<<<aggGrid, 256>>>();

    // fork: stats on side stream, overlapped with semantic GEMMs
    cudaEventRecord(g_evC, 0);
    cudaStreamWaitEvent(g_s2, g_evC, 0);

    dim3 semGrid(mmGrid, 4);
    sem_mma_kernel<<<semGrid, 256, SEM_SMEM_BYTES>>>(bk, q);

    dim3 stGrid2((N + 511) / 512, 2);
    stats_kernel<<<stGrid2, 256, 0, g_s2>>>();

    // join: bnparam needs stats (s2) + scores (stream 0)
    cudaEventRecord(g_evD, g_s2);
    cudaStreamWaitEvent(0, g_evD, 0);

    bnparam_kernel<<<1, 256>>>(gamma, beta);

    combine_norm_kernel<<<4096, 256>>>(out);
}

// round 16
// speedup vs baseline: 1.0337x; 1.0337x over previous
#include <cuda_runtime.h>
#include <cuda_fp16.h>
#include <math.h>
#include <stdint.h>

#define N 100000
#define E 400000
#define HID 128
#define NH 8

// ---------------- device scratch ----------------
__device__ __align__(16) uint32_t g_h16[2][(size_t)N * 64];  // fp16x2 projected features
__device__ __align__(16) float g_alphaS[4][(size_t)N * NH];  // [n*8 + h]
__device__ __align__(16) float g_alphaD[4][(size_t)N * NH];
__device__ int   g_deg[4][N];
__device__ int   g_rowptr[4][N + 1];
__device__ int   g_bsum[4][128];
__device__ int   g_boff[4][128];
__device__ int   g_srcs[4][E];
__device__ __align__(16) uint32_t g_of[4][(size_t)N * 64];   // fp16x2 o (single copy)
__device__ float g_score[4];
__device__ float g_attn[4];
__device__ float g_st[2][5][HID];   // s0,s1,ss0,ss1,cross per type per column
__device__ float g_scale[2][HID];
__device__ float g_shift[2][HID];
// W as pre-packed f16 MMA B-fragments: [which][((whalf*8+nt)*8+kc)*32+lane] = {b0,b1}
__device__ __align__(16) uint2 g_Wfrag[3][4096];

// ---------------- helpers ----------------
__device__ __forceinline__ uint32_t pack_h2(float x, float y) {
    __half2 p = __floats2half2_rn(x, y);
    return *reinterpret_cast<uint32_t*>(&p);
}

__device__ __forceinline__ void unpack_h2(uint32_t u, float& a, float& b) {
    __half2 p = *reinterpret_cast<__half2*>(&u);
    a = __low2float(p);
    b = __high2float(p);
}

// exact hi/lo split of fp32 pair into two f16 pairs
__device__ __forceinline__ void split2h(float x, float y, uint32_t& hi, uint32_t& lo) {
    __half hx = __float2half_rn(x), hy = __float2half_rn(y);
    __half2 hp(hx, hy);
    hi = *reinterpret_cast<uint32_t*>(&hp);
    lo = pack_h2(x - __half2float(hx), y - __half2float(hy));
}

__device__ __forceinline__ void mma_f16(float* d, const uint32_t* a, uint32_t b0, uint32_t b1) {
    asm volatile(
        "mma.sync.aligned.m16n8k16.row.col.f32.f16.f16.f32 "
        "{%0,%1,%2,%3}, {%4,%5,%6,%7}, {%8,%9}, {%0,%1,%2,%3};"
        : "+f"(d[0]), "+f"(d[1]), "+f"(d[2]), "+f"(d[3])
        : "r"(a[0]), "r"(a[1]), "r"(a[2]), "r"(a[3]), "r"(b0), "r"(b1));
}

__device__ __forceinline__ void ldsm4(uint32_t* r, uint32_t addr) {
    asm volatile("ldmatrix.sync.aligned.m8n8.x4.shared.b16 {%0,%1,%2,%3}, [%4];"
        : "=r"(r[0]), "=r"(r[1]), "=r"(r[2]), "=r"(r[3]) : "r"(addr));
}

__device__ __forceinline__ uint32_t smem_u32(const void* p) {
    uint32_t a;
    asm("{ .reg .u64 t; cvta.to.shared.u64 t, %1; cvt.u32.u64 %0, t; }" : "=r"(a) : "l"(p));
    return a;
}

// stage a 128-row x 64-u32 tile (pitch 68 u32) from global via cp.async, 16B chunks
__device__ __forceinline__ void stage_tile(uint32_t sbase_bytes, const uint32_t* __restrict__ src,
                                           int row0, int arows) {
    int t = threadIdx.x;
#pragma unroll
    for (int i = 0; i < 8; i++) {
        int idx = i * 256 + t;            // [0, 2048)
        int r = idx >> 4, c = idx & 15;
        int gr = row0 + r;
        bool ok = (gr < arows);
        const uint32_t* s = src + (size_t)(ok ? gr : 0) * 64 + c * 4;
        uint32_t dst = sbase_bytes + (r * 68 + c * 4) * 4;
        int sz = ok ? 16 : 0;
        asm volatile("cp.async.cg.shared.global [%0], [%1], 16, %2;" :: "r"(dst), "l"(s), "r"(sz));
    }
}

#define CP_COMMIT_WAIT() do { \
    asm volatile("cp.async.commit_group;" ::: "memory"); \
    asm volatile("cp.async.wait_group 0;" ::: "memory"); \
} while (0)

// ---------------- f16 GEMM compute on staged A tiles + global W fragments ----------------
template <int NPASS>
__device__ __forceinline__ void gemm_compute(uint32_t sb, const int* AO,
                                             const uint2* __restrict__ Wf, float* acc) {
    int t = threadIdx.x;
    int wid = t >> 5, lane = t & 31;
    int wr = (wid >> 1) * 32, whalf = wid & 1;
    int g = lane >> 3;
    int rowoff = (g & 1) * 8 + (lane & 7);
    int koff = (g >> 1) * 16;

#pragma unroll
    for (int i = 0; i < 64; i++) acc[i] = 0.f;

#pragma unroll
    for (int p = 0; p < NPASS; p++) {
        uint32_t abase = sb + (uint32_t)(AO[p] + (wr + rowoff) * 68) * 4 + koff;
        const uint2* Wb = Wf + whalf * 2048 + lane;
#pragma unroll 2
        for (int kc = 0; kc < 8; kc++) {
            uint32_t a0[4], a1[4];
            ldsm4(a0, abase + kc * 32);
            ldsm4(a1, abase + kc * 32 + 16 * 68 * 4);
#pragma unroll
            for (int nt = 0; nt < 8; nt++) {
                uint2 b = __ldg(&Wb[(nt * 8 + kc) * 32]);
                mma_f16(acc + (0 * 8 + nt) * 4, a0, b.x, b.y);
                mma_f16(acc + (1 * 8 + nt) * 4, a1, b.x, b.y);
            }
        }
    }
}

// ---------------- weight prep: pack f16 MMA B fragments ----------------
__global__ void prep_w_kernel(const float* __restrict__ W_a,
                              const float* __restrict__ W_b,
                              const float* __restrict__ Wk) {
    int which = blockIdx.x;
    const float* W = which == 0 ? W_a : (which == 1 ? W_b : Wk);
    for (int i = threadIdx.x; i < 4096; i += blockDim.x) {
        int lane = i & 31;
        int kc = (i >> 5) & 7;
        int nt = (i >> 8) & 7;
        int whalf = (i >> 11) & 1;
        int n = whalf * 64 + nt * 8 + (lane >> 2);
        int kw0 = kc * 8 + (lane & 3);
        int kw1 = kw0 + 4;
        float x0 = W[(2 * kw0) * 128 + n], x1 = W[(2 * kw0 + 1) * 128 + n];
        float y0 = W[(2 * kw1) * 128 + n], y1 = W[(2 * kw1 + 1) * 128 + n];
        g_Wfrag[which][i] = make_uint2(pack_h2(x0, x1), pack_h2(y0, y1));
    }
}

// smem u32-index layout (proj): AH, AL pitch-68 tiles + satt
#define SW_AH 0
#define SW_AL 8704
#define SW_SATT 17408
#define PROJ_SMEM_BYTES ((17408 + 512) * 4)

// sem layout: AH + red
#define SEM_RED 8704
#define SEM_SMEM_BYTES ((8704 + 64) * 4)

// ---------------- projection (both types, blockIdx.y = type), 2-pass f16 ----------------
__global__ void __launch_bounds__(256, 2) proj_mma_kernel(
    const float* __restrict__ x_a, const float* __restrict__ x_b,
    const float* __restrict__ b_a, const float* __restrict__ b_b,
    const float* __restrict__ atA0, const float* __restrict__ atA1,
    const float* __restrict__ atA2, const float* __restrict__ atA3,
    const float* __restrict__ atB0, const float* __restrict__ atB1,
    const float* __restrict__ atB2, const float* __restrict__ atB3) {
    extern __shared__ uint32_t smemu[];
    float* smemf = (float*)smemu;
    float* satt = smemf + SW_SATT;
    uint32_t sb = smem_u32(smemu);

    int type = blockIdx.y;
    const float* X = type == 0 ? x_a : x_b;
    const float* bias = type == 0 ? b_a : b_b;

    int t = threadIdx.x;
    for (int i = t; i < 512; i += 256) {
        int arr = i >> 7, col = i & 127;
        const float* p;
        if (type == 0)
            p = arr == 0 ? atA0 : arr == 1 ? atA1 : arr == 2 ? atA2 : atA3;
        else
            p = arr == 0 ? atB0 : arr == 1 ? atB1 : arr == 2 ? atB2 : atB3;
        satt[i] = __ldg(&p[col]);
    }

    int row0 = blockIdx.x * 128;
    const float4* X4 = (const float4*)X;
#pragma unroll
    for (int i = 0; i < 16; i++) {
        int idx = i * 256 + t;
        int r = idx >> 5, c4 = idx & 31;
        int gr = row0 + r;
        float4 v = make_float4(0.f, 0.f, 0.f, 0.f);
        if (gr < N) v = X4[(size_t)gr * 32 + c4];
        uint32_t h0, l0, h1, l1;
        split2h(v.x, v.y, h0, l0);
        split2h(v.z, v.w, h1, l1);
        int base = r * 68 + c4 * 2;
        smemu[SW_AH + base] = h0;
        smemu[SW_AH + base + 1] = h1;
        smemu[SW_AL + base] = l0;
        smemu[SW_AL + base + 1] = l1;
    }
    __syncthreads();

    float acc[64];
    const int AO[2] = {SW_AH, SW_AL};
    gemm_compute<2>(sb, AO, g_Wfrag[type], acc);

    uint32_t* Hout = g_h16[type];
    int rS0 = type == 0 ? 0 : 1, rS1 = type == 0 ? 2 : 3;
    int rD0 = type == 0 ? 1 : 0, rD1 = type == 0 ? 2 : 3;

    int wid = t >> 5, lane = t & 31;
    int wr = (wid >> 1) * 32, wc = (wid & 1) * 64;

    __syncthreads();  // done reading A smem; reuse as vbuf (pitch 134 floats)

#pragma unroll
    for (int rt = 0; rt < 2; rt++) {
#pragma unroll
        for (int hr = 0; hr < 2; hr++) {
            int lrow = wr + rt * 16 + hr * 8 + (lane >> 2);
            int grow = row0 + lrow;
#pragma unroll
            for (int nt = 0; nt < 8; nt++) {
                int col = wc + nt * 8 + (lane & 3) * 2;
                float2 bb = __ldg((const float2*)(bias + col));
                float v0 = acc[(rt * 8 + nt) * 4 + hr * 2] + bb.x;
                float v1 = acc[(rt * 8 + nt) * 4 + hr * 2 + 1] + bb.y;
                if (grow < N)
                    Hout[(size_t)grow * 64 + (col >> 1)] = pack_h2(v0, v1);
                *(float2*)(smemf + lrow * 134 + col) = make_float2(v0, v1);
            }
        }
    }
    __syncthreads();

    if (t < 128) {
        int node = row0 + t;
        if (node < N) {
            const float* vrow = smemf + t * 134;
            float* aS0 = &g_alphaS[rS0][0];
            float* aS1 = &g_alphaS[rS1][0];
            float* aD0 = &g_alphaD[rD0][0];
            float* aD1 = &g_alphaD[rD1][0];
#pragma unroll
            for (int h = 0; h < 8; h++) {
                float p0 = 0.f, p1 = 0.f, p2 = 0.f, p3 = 0.f;
#pragma unroll
                for (int i = 0; i < 16; i++) {
                    int col = h * 16 + i;
                    float v = vrow[col];
                    p0 = fmaf(v, satt[0 * 128 + col], p0);
                    p1 = fmaf(v, satt[1 * 128 + col], p1);
                    p2 = fmaf(v, satt[2 * 128 + col], p2);
                    p3 = fmaf(v, satt[3 * 128 + col], p3);
                }
                aS0[node * 8 + h] = p0;
                aS1[node * 8 + h] = p1;
                aD0[node * 8 + h] = p2;
                aD1[node * 8 + h] = p3;
            }
        }
    }
}

// ---------------- semantic score (blockIdx.y = rel), single-pass f16 ----------------
__global__ void __launch_bounds__(256, 2) sem_mma_kernel(
    const float* __restrict__ bk, const float* __restrict__ q) {
    extern __shared__ uint32_t smemu[];
    float* red = (float*)smemu + SEM_RED;
    uint32_t sb = smem_u32(smemu);
    int rel = blockIdx.y;
    int row0 = blockIdx.x * 128;

    stage_tile(sb, g_of[rel], row0, N);
    CP_COMMIT_WAIT();
    __syncthreads();

    float acc[64];
    const int AO[1] = {0};
    gemm_compute<1>(sb, AO, g_Wfrag[2], acc);

    int t = threadIdx.x;
    int wid = t >> 5, lane = t & 31;
    int wr = (wid >> 1) * 32, wc = (wid & 1) * 64;

    float local = 0.f;
#pragma unroll
    for (int rt = 0; rt < 2; rt++) {
#pragma unroll
        for (int hr = 0; hr < 2; hr++) {
            int grow = row0 + wr + rt * 16 + hr * 8 + (lane >> 2);
            if (grow < N) {
#pragma unroll
                for (int nt = 0; nt < 8; nt++) {
                    int col = wc + nt * 8 + (lane & 3) * 2;
                    float2 bb = __ldg((const float2*)(bk + col));
                    float2 qq = __ldg((const float2*)(q + col));
                    float v0 = acc[(rt * 8 + nt) * 4 + hr * 2] + bb.x;
                    float v1 = acc[(rt * 8 + nt) * 4 + hr * 2 + 1] + bb.y;
                    local += tanhf(v0) * qq.x + tanhf(v1) * qq.y;
                }
            }
        }
    }
#pragma unroll
    for (int off = 16; off >= 1; off >>= 1)
        local += __shfl_down_sync(0xffffffff, local, off);
    __syncthreads();
    if (lane == 0) red[wid] = local;
    __syncthreads();
    if (t == 0) {
        float s = 0.f;
#pragma unroll
        for (int w = 0; w < 8; w++) s += red[w];
        atomicAdd(&g_score[rel], s);
    }
}

// ---------------- init ----------------
__global__ void init_kernel() {
    int i = blockIdx.x * blockDim.x + threadIdx.x;
    int stride = gridDim.x * blockDim.x;
    int* degf = &g_deg[0][0];
    for (int k = i; k < 4 * N; k += stride) degf[k] = 0;
    if (i < 4) g_score[i] = 0.f;
    if (i < 2 * 5 * HID) (&g_st[0][0][0])[i] = 0.f;
}

// ---------------- CSR build ----------------
__global__ void count_kernel(const int* __restrict__ e0, const int* __restrict__ e1,
                             const int* __restrict__ e2, const int* __restrict__ e3) {
    int rel = blockIdx.y;
    const int* ei = rel == 0 ? e0 : rel == 1 ? e1 : rel == 2 ? e2 : e3;
    int e = blockIdx.x * blockDim.x + threadIdx.x;
    if (e < E) atomicAdd(&g_deg[rel][ei[E + e]], 1);
}

__global__ void scan1_kernel() {
    int rel = blockIdx.y;
    int i = blockIdx.x * 1024 + threadIdx.x;
    int lane = threadIdx.x & 31, wid = threadIdx.x >> 5;
    int v = (i < N) ? g_deg[rel][i] : 0;
    int x = v;
#pragma unroll
    for (int o = 1; o < 32; o <<= 1) {
        int y = __shfl_up_sync(0xffffffff, x, o);
        if (lane >= o) x += y;
    }
    __shared__ int ws[32];
    if (lane == 31) ws[wid] = x;
    __syncthreads();
    if (wid == 0) {
        int s = ws[lane];
#pragma unroll
        for (int o = 1; o < 32; o <<= 1) {
            int y = __shfl_up_sync(0xffffffff, s, o);
            if (lane >= o) s += y;
        }
        ws[lane] = s;
    }
    __syncthreads();
    int incl = x + (wid ? ws[wid - 1] : 0);
    if (i < N) g_rowptr[rel][i] = incl - v;
    if (threadIdx.x == 1023) g_bsum[rel][blockIdx.x] = incl;
}

__global__ void scan2_kernel() {
    int rel = blockIdx.x;
    int t = threadIdx.x;  // 128
    int lane = t & 31, wid = t >> 5;
    int v = (t < 98) ? g_bsum[rel][t] : 0;
    int x = v;
#pragma unroll
    for (int o = 1; o < 32; o <<= 1) {
        int y = __shfl_up_sync(0xffffffff, x, o);
        if (lane >= o) x += y;
    }
    __shared__ int ws[4];
    if (lane == 31) ws[wid] = x;
    __syncthreads();
    int prefix = 0;
    for (int k = 0; k < wid; k++) prefix += ws[k];
    int incl = x + prefix;
    if (t < 98) g_boff[rel][t] = incl - v;
    if (t == 0) g_rowptr[rel][N] = E;
}

__global__ void scan3_kernel() {
    int rel = blockIdx.y;
    int i = blockIdx.x * 1024 + threadIdx.x;
    if (i < N) {
        g_rowptr[rel][i] += g_boff[rel][blockIdx.x];
        g_deg[rel][i] = 0;  // reset cursor for scatter
    }
}

__global__ void scatter_kernel(const int* __restrict__ e0, const int* __restrict__ e1,
                               const int* __restrict__ e2, const int* __restrict__ e3) {
    int rel = blockIdx.y;
    const int* ei = rel == 0 ? e0 : rel == 1 ? e1 : rel == 2 ? e2 : e3;
    int e = blockIdx.x * blockDim.x + threadIdx.x;
    if (e < E) {
        int s = ei[e], d = ei[E + e];
        int pos = g_rowptr[rel][d] + atomicAdd(&g_deg[rel][d], 1);
        g_srcs[rel][pos] = s;
    }
}

// ---------------- aggregate: TWO nodes per warp (16 lanes x 8 dims each) ----------------
__global__ void aggregate_kernel() {
    int rel = blockIdx.y;
    const uint32_t* hs = g_h16[(rel == 0 || rel == 2) ? 0 : 1];
    int w = (blockIdx.x * blockDim.x + threadIdx.x) >> 5;
    int lane = threadIdx.x & 31;
    int n = w * 2 + (lane >> 4);
    if (n >= N) return;
    int sl = lane & 15;       // sublane: dims [sl*8, sl*8+8)
    int h = sl >> 1;

    const float* aS = g_alphaS[rel];
    float ad = g_alphaD[rel][n * 8 + h];
    int beg = g_rowptr[rel][n], end = g_rowptr[rel][n + 1];
    const int* srcs = g_srcs[rel];

    float den = 0.f;
    float a0v[8];
#pragma unroll
    for (int i = 0; i < 8; i++) a0v[i] = 0.f;

    int e = beg;
    for (; e + 2 <= end; e += 2) {
        int s0 = srcs[e], s1 = srcs[e + 1];
        float a0 = aS[s0 * 8 + h] + ad;
        float a1 = aS[s1 * 8 + h] + ad;
        a0 = a0 > 0.f ? a0 : 0.2f * a0;
        a1 = a1 > 0.f ? a1 : 0.2f * a1;
        float w0 = __expf(a0), w1 = __expf(a1);
        den += w0 + w1;
        uint4 u0 = *reinterpret_cast<const uint4*>(hs + (size_t)s0 * 64 + sl * 4);
        uint4 u1 = *reinterpret_cast<const uint4*>(hs + (size_t)s1 * 64 + sl * 4);
        float f[8], g[8];
        unpack_h2(u0.x, f[0], f[1]); unpack_h2(u0.y, f[2], f[3]);
        unpack_h2(u0.z, f[4], f[5]); unpack_h2(u0.w, f[6], f[7]);
        unpack_h2(u1.x, g[0], g[1]); unpack_h2(u1.y, g[2], g[3]);
        unpack_h2(u1.z, g[4], g[5]); unpack_h2(u1.w, g[6], g[7]);
#pragma unroll
        for (int i = 0; i < 8; i++)
            a0v[i] = fmaf(w0, f[i], fmaf(w1, g[i], a0v[i]));
    }
    if (e < end) {
        int s0 = srcs[e];
        float a0 = aS[s0 * 8 + h] + ad;
        a0 = a0 > 0.f ? a0 : 0.2f * a0;
        float w0 = __expf(a0);
        den += w0;
        uint4 u0 = *reinterpret_cast<const uint4*>(hs + (size_t)s0 * 64 + sl * 4);
        float f[8];
        unpack_h2(u0.x, f[0], f[1]); unpack_h2(u0.y, f[2], f[3]);
        unpack_h2(u0.z, f[4], f[5]); unpack_h2(u0.w, f[6], f[7]);
#pragma unroll
        for (int i = 0; i < 8; i++)
            a0v[i] = fmaf(w0, f[i], a0v[i]);
    }
    float inv = 1.f / (den + 1e-16f);
    uint4 o;
    o.x = pack_h2(fmaxf(a0v[0] * inv, 0.f), fmaxf(a0v[1] * inv, 0.f));
    o.y = pack_h2(fmaxf(a0v[2] * inv, 0.f), fmaxf(a0v[3] * inv, 0.f));
    o.z = pack_h2(fmaxf(a0v[4] * inv, 0.f), fmaxf(a0v[5] * inv, 0.f));
    o.w = pack_h2(fmaxf(a0v[6] * inv, 0.f), fmaxf(a0v[7] * inv, 0.f));
    *reinterpret_cast<uint4*>(&g_of[rel][(size_t)n * 64 + sl * 4]) = o;
}

// ---------------- BN stats from fp16 o (5 stats per type per column) ----------------
__global__ void stats_kernel() {
    int type = blockIdx.y;
    int rel0 = type == 0 ? 1 : 0;
    int rel1 = type == 0 ? 2 : 3;
    int t = threadIdx.x;        // 256
    int cp = t & 63, rg = t >> 6;
    int r0 = blockIdx.x * 512;
    int rend = r0 + 512;
    if (rend > N) rend = N;

    float s0a = 0.f, s1a = 0.f, ss0a = 0.f, ss1a = 0.f, cxa = 0.f;
    float s0b = 0.f, s1b = 0.f, ss0b = 0.f, ss1b = 0.f, cxb = 0.f;
    for (int r = r0 + rg; r < rend; r += 4) {
        uint32_t u0 = g_of[rel0][(size_t)r * 64 + cp];
        uint32_t u1 = g_of[rel1][(size_t)r * 64 + cp];
        float xa, xb, ya, yb;
        unpack_h2(u0, xa, xb);
        unpack_h2(u1, ya, yb);
        s0a += xa; s1a += ya; ss0a += xa * xa; ss1a += ya * ya; cxa += xa * ya;
        s0b += xb; s1b += yb; ss0b += xb * xb; ss1b += yb * yb; cxb += xb * yb;
    }
    __shared__ float red[4][64][10];
    float* my = red[rg][cp];
    my[0] = s0a; my[1] = s1a; my[2] = ss0a; my[3] = ss1a; my[4] = cxa;
    my[5] = s0b; my[6] = s1b; my[7] = ss0b; my[8] = ss1b; my[9] = cxb;
    __syncthreads();
    if (rg == 0) {
#pragma unroll
        for (int k = 0; k < 10; k++) {
            float v = red[0][cp][k] + red[1][cp][k] + red[2][cp][k] + red[3][cp][k];
            int stat = k % 5;
            int col = cp * 2 + (k / 5);
            atomicAdd(&g_st[type][stat][col], v);
        }
    }
}

// ---------------- BN params (computes semantic attn inline) ----------------
__global__ void bnparam_kernel(const float* __restrict__ gamma,
                               const float* __restrict__ beta) {
    int t = threadIdx.x;  // 256
    int type = t >> 7, j = t & 127;
    int r0 = type == 0 ? 1 : 0, r1 = type == 0 ? 2 : 3;
    float sc0 = g_score[r0] / (float)N, sc1 = g_score[r1] / (float)N;
    float m = fmaxf(sc0, sc1);
    float e0 = expf(sc0 - m), e1 = expf(sc1 - m);
    float a0 = e0 / (e0 + e1), a1 = e1 / (e0 + e1);
    if (j == 0) {
        g_attn[type * 2 + 0] = a0;
        g_attn[type * 2 + 1] = a1;
    }
    float s0 = g_st[type][0][j], s1 = g_st[type][1][j];
    float ss0 = g_st[type][2][j], ss1 = g_st[type][3][j], cx = g_st[type][4][j];
    float mu = (a0 * s0 + a1 * s1) / (float)N;
    float ex2 = (a0 * a0 * ss0 + 2.f * a0 * a1 * cx + a1 * a1 * ss1) / (float)N;
    float var = ex2 - mu * mu;
    float rstd = rsqrtf(var + 1e-5f);
    float sc = rstd * gamma[j];
    g_scale[type][j] = sc;
    g_shift[type][j] = beta[j] - mu * sc;
}

// ---------------- fused combine + normalize (reads fp16 o) ----------------
__global__ void combine_norm_kernel(float* __restrict__ out) {
    int stride = gridDim.x * blockDim.x;
    int total = 2 * N * 32;  // uint2 (4 cols) units
    for (int i = blockIdx.x * blockDim.x + threadIdx.x; i < total; i += stride) {
        int type = (i >= N * 32) ? 1 : 0;
        int local = i - type * N * 32;
        const uint2* o0 = (const uint2*)(type == 0 ? g_of[1] : g_of[0]);
        const uint2* o1 = (const uint2*)(type == 0 ? g_of[2] : g_of[3]);
        float a0 = g_attn[type * 2 + 0], a1 = g_attn[type * 2 + 1];
        uint2 u0 = o0[local], u1 = o1[local];
        float x0, x1, x2, x3, y0, y1, y2, y3;
        unpack_h2(u0.x, x0, x1);
        unpack_h2(u0.y, x2, x3);
        unpack_h2(u1.x, y0, y1);
        unpack_h2(u1.y, y2, y3);
        int j = (local & 31) * 4;
        const float* sc = g_scale[type];
        const float* sf = g_shift[type];
        float4 r;
        r.x = (a0 * x0 + a1 * y0) * sc[j + 0] + sf[j + 0];
        r.y = (a0 * x1 + a1 * y1) * sc[j + 1] + sf[j + 1];
        r.z = (a0 * x2 + a1 * y2) * sc[j + 2] + sf[j + 2];
        r.w = (a0 * x3 + a1 * y3) * sc[j + 3] + sf[j + 3];
        ((float4*)out)[i] = r;
    }
}

// ---------------- host ----------------
static cudaStream_t g_s2 = 0;
static cudaEvent_t g_evA, g_evB, g_evC, g_evD;

extern "C" void kernel_launch(void* const* d_in, const int* in_sizes, int n_in,
                              void* d_out, int out_size) {
    const float* x_a = (const float*)d_in[0];
    const float* x_b = (const float*)d_in[1];
    const int* ei_ab = (const int*)d_in[2];
    const int* ei_ba = (const int*)d_in[3];
    const int* ei_aa = (const int*)d_in[4];
    const int* ei_bb = (const int*)d_in[5];
    const float* W_a = (const float*)d_in[6];
    const float* b_a = (const float*)d_in[7];
    const float* W_b = (const float*)d_in[8];
    const float* b_b = (const float*)d_in[9];
    const float* att_ab_s = (const float*)d_in[10];
    const float* att_ab_d = (const float*)d_in[11];
    const float* att_ba_s = (const float*)d_in[12];
    const float* att_ba_d = (const float*)d_in[13];
    const float* att_aa_s = (const float*)d_in[14];
    const float* att_aa_d = (const float*)d_in[15];
    const float* att_bb_s = (const float*)d_in[16];
    const float* att_bb_d = (const float*)d_in[17];
    const float* Wk = (const float*)d_in[18];
    const float* bk = (const float*)d_in[19];
    const float* q  = (const float*)d_in[20];
    const float* gamma = (const float*)d_in[21];
    const float* beta  = (const float*)d_in[22];
    float* out = (float*)d_out;

    if (g_s2 == 0) {
        cudaStreamCreateWithFlags(&g_s2, cudaStreamNonBlocking);
        cudaEventCreateWithFlags(&g_evA, cudaEventDisableTiming);
        cudaEventCreateWithFlags(&g_evB, cudaEventDisableTiming);
        cudaEventCreateWithFlags(&g_evC, cudaEventDisableTiming);
        cudaEventCreateWithFlags(&g_evD, cudaEventDisableTiming);
        cudaFuncSetAttribute(proj_mma_kernel, cudaFuncAttributeMaxDynamicSharedMemorySize, PROJ_SMEM_BYTES);
        cudaFuncSetAttribute(sem_mma_kernel, cudaFuncAttributeMaxDynamicSharedMemorySize, SEM_SMEM_BYTES);
    }

    // fork: init + CSR chain on side stream, overlapped with weight prep + projection
    cudaEventRecord(g_evA, 0);
    cudaStreamWaitEvent(g_s2, g_evA, 0);

    init_kernel<<<512, 256, 0, g_s2>>>();

    prep_w_kernel<<<3, 256>>>(W_a, W_b, Wk);

    int mmGrid = (N + 127) / 128;  // 782
    dim3 pGrid(mmGrid, 2);
    proj_mma_kernel<<<pGrid, 256, PROJ_SMEM_BYTES>>>(
        x_a, x_b, b_a, b_b,
        att_ab_s, att_aa_s, att_ba_d, att_aa_d,
        att_ba_s, att_bb_s, att_ab_d, att_bb_d);

    dim3 eGrid((E + 255) / 256, 4);
    dim3 sGrid((N + 1023) / 1024, 4);
    count_kernel<<<eGrid, 256, 0, g_s2>>>(ei_ab, ei_ba, ei_aa, ei_bb);
    scan1_kernel<<<sGrid, 1024, 0, g_s2>>>();
    scan2_kernel<<<4, 128, 0, g_s2>>>();
    scan3_kernel<<<sGrid, 1024, 0, g_s2>>>();
    scatter_kernel<<<eGrid, 256, 0, g_s2>>>(ei_ab, ei_ba, ei_aa, ei_bb);

    // join: aggregate needs alphas (stream 0) + CSR (s2); also orders init's
    // g_score/g_st zeroing before sem/stats.
    cudaEventRecord(g_evB, g_s2);
    cudaStreamWaitEvent(0, g_evB, 0);

    dim3 aggGrid(((N + 1) / 2 * 32 + 255) / 256, 4);
    aggregate_kernel<<<aggGrid, 256>>>();

    // fork: stats on side stream, overlapped with semantic GEMMs
    cudaEventRecord(g_evC, 0);
    cudaStreamWaitEvent(g_s2, g_evC, 0);

    dim3 semGrid(mmGrid, 4);
    sem_mma_kernel<<<semGrid, 256, SEM_SMEM_BYTES>>>(bk, q);

    dim3 stGrid2((N + 511) / 512, 2);
    stats_kernel<<<stGrid2, 256, 0, g_s2>>>();

    // join: bnparam needs stats (s2) + scores (stream 0)
    cudaEventRecord(g_evD, g_s2);
    cudaStreamWaitEvent(0, g_evD, 0);

    bnparam_kernel<<<1, 256>>>(gamma, beta);

    combine_norm_kernel<<<4096, 256>>>(out);
}

// round 17
// speedup vs baseline: 1.0641x; 1.0294x over previous
#include <cuda_runtime.h>
#include <cuda_fp16.h>
#include <math.h>
#include <stdint.h>

#define N 100000
#define E 400000
#define HID 128
#define NH 8

// ---------------- device scratch ----------------
__device__ __align__(16) uint32_t g_h16[2][(size_t)N * 64];  // fp16x2 projected features
__device__ __align__(16) float g_alphaS[4][(size_t)N * NH];  // [n*8 + h]
__device__ __align__(16) float g_alphaD[4][(size_t)N * NH];
__device__ int   g_deg[4][N];
__device__ int   g_rowptr[4][N + 1];
__device__ int   g_bsum[4][128];
__device__ int   g_boff[4][128];
__device__ int   g_srcs[4][E];
__device__ __align__(16) uint32_t g_of[4][(size_t)N * 64];   // fp16x2 o (single copy)
__device__ float g_score[4];
__device__ float g_attn[4];
__device__ float g_st[2][5][HID];   // s0,s1,ss0,ss1,cross per type per column
__device__ float g_scale[2][HID];
__device__ float g_shift[2][HID];
// W as pre-packed f16 MMA B-fragments: [which][((whalf*8+nt)*8+kc)*32+lane] = {b0,b1}
__device__ __align__(16) uint2 g_Wfrag[3][4096];

// ---------------- helpers ----------------
__device__ __forceinline__ uint32_t pack_h2(float x, float y) {
    __half2 p = __floats2half2_rn(x, y);
    return *reinterpret_cast<uint32_t*>(&p);
}

__device__ __forceinline__ void unpack_h2(uint32_t u, float& a, float& b) {
    __half2 p = *reinterpret_cast<__half2*>(&u);
    a = __low2float(p);
    b = __high2float(p);
}

__device__ __forceinline__ void mma_f16(float* d, const uint32_t* a, uint32_t b0, uint32_t b1) {
    asm volatile(
        "mma.sync.aligned.m16n8k16.row.col.f32.f16.f16.f32 "
        "{%0,%1,%2,%3}, {%4,%5,%6,%7}, {%8,%9}, {%0,%1,%2,%3};"
        : "+f"(d[0]), "+f"(d[1]), "+f"(d[2]), "+f"(d[3])
        : "r"(a[0]), "r"(a[1]), "r"(a[2]), "r"(a[3]), "r"(b0), "r"(b1));
}

__device__ __forceinline__ void ldsm4(uint32_t* r, uint32_t addr) {
    asm volatile("ldmatrix.sync.aligned.m8n8.x4.shared.b16 {%0,%1,%2,%3}, [%4];"
        : "=r"(r[0]), "=r"(r[1]), "=r"(r[2]), "=r"(r[3]) : "r"(addr));
}

__device__ __forceinline__ uint32_t smem_u32(const void* p) {
    uint32_t a;
    asm("{ .reg .u64 t; cvta.to.shared.u64 t, %1; cvt.u32.u64 %0, t; }" : "=r"(a) : "l"(p));
    return a;
}

// stage a 128-row x 64-u32 tile (pitch 68 u32) from global via cp.async, 16B chunks
__device__ __forceinline__ void stage_tile(uint32_t sbase_bytes, const uint32_t* __restrict__ src,
                                           int row0, int arows) {
    int t = threadIdx.x;
#pragma unroll
    for (int i = 0; i < 8; i++) {
        int idx = i * 256 + t;            // [0, 2048)
        int r = idx >> 4, c = idx & 15;
        int gr = row0 + r;
        bool ok = (gr < arows);
        const uint32_t* s = src + (size_t)(ok ? gr : 0) * 64 + c * 4;
        uint32_t dst = sbase_bytes + (r * 68 + c * 4) * 4;
        int sz = ok ? 16 : 0;
        asm volatile("cp.async.cg.shared.global [%0], [%1], 16, %2;" :: "r"(dst), "l"(s), "r"(sz));
    }
}

#define CP_COMMIT_WAIT() do { \
    asm volatile("cp.async.commit_group;" ::: "memory"); \
    asm volatile("cp.async.wait_group 0;" ::: "memory"); \
} while (0)

// ---------------- f16 GEMM compute on staged A tile + global W fragments ----------------
__device__ __forceinline__ void gemm_compute1(uint32_t sb, int ao,
                                              const uint2* __restrict__ Wf, float* acc) {
    int t = threadIdx.x;
    int wid = t >> 5, lane = t & 31;
    int wr = (wid >> 1) * 32, whalf = wid & 1;
    int g = lane >> 3;
    int rowoff = (g & 1) * 8 + (lane & 7);
    int koff = (g >> 1) * 16;

#pragma unroll
    for (int i = 0; i < 64; i++) acc[i] = 0.f;

    uint32_t abase = sb + (uint32_t)(ao + (wr + rowoff) * 68) * 4 + koff;
    const uint2* Wb = Wf + whalf * 2048 + lane;
#pragma unroll 2
    for (int kc = 0; kc < 8; kc++) {
        uint32_t a0[4], a1[4];
        ldsm4(a0, abase + kc * 32);
        ldsm4(a1, abase + kc * 32 + 16 * 68 * 4);
#pragma unroll
        for (int nt = 0; nt < 8; nt++) {
            uint2 b = __ldg(&Wb[(nt * 8 + kc) * 32]);
            mma_f16(acc + (0 * 8 + nt) * 4, a0, b.x, b.y);
            mma_f16(acc + (1 * 8 + nt) * 4, a1, b.x, b.y);
        }
    }
}

// ---------------- weight prep: pack f16 MMA B fragments ----------------
__global__ void prep_w_kernel(const float* __restrict__ W_a,
                              const float* __restrict__ W_b,
                              const float* __restrict__ Wk) {
    int which = blockIdx.x;
    const float* W = which == 0 ? W_a : (which == 1 ? W_b : Wk);
    for (int i = threadIdx.x; i < 4096; i += blockDim.x) {
        int lane = i & 31;
        int kc = (i >> 5) & 7;
        int nt = (i >> 8) & 7;
        int whalf = (i >> 11) & 1;
        int n = whalf * 64 + nt * 8 + (lane >> 2);
        int kw0 = kc * 8 + (lane & 3);
        int kw1 = kw0 + 4;
        float x0 = W[(2 * kw0) * 128 + n], x1 = W[(2 * kw0 + 1) * 128 + n];
        float y0 = W[(2 * kw1) * 128 + n], y1 = W[(2 * kw1 + 1) * 128 + n];
        g_Wfrag[which][i] = make_uint2(pack_h2(x0, x1), pack_h2(y0, y1));
    }
}

// smem u32-index layout (proj): AH pitch-68 tile + satt; total sized for vbuf reuse
#define SW_AH 0
#define SW_SATT 17408
#define PROJ_SMEM_BYTES ((17408 + 512) * 4)

// sem layout: AH + red
#define SEM_RED 8704
#define SEM_SMEM_BYTES ((8704 + 64) * 4)

// ---------------- projection (both types, blockIdx.y = type), single-pass f16 ----------
__global__ void __launch_bounds__(256, 2) proj_mma_kernel(
    const float* __restrict__ x_a, const float* __restrict__ x_b,
    const float* __restrict__ b_a, const float* __restrict__ b_b,
    const float* __restrict__ atA0, const float* __restrict__ atA1,
    const float* __restrict__ atA2, const float* __restrict__ atA3,
    const float* __restrict__ atB0, const float* __restrict__ atB1,
    const float* __restrict__ atB2, const float* __restrict__ atB3) {
    extern __shared__ uint32_t smemu[];
    float* smemf = (float*)smemu;
    float* satt = smemf + SW_SATT;
    uint32_t sb = smem_u32(smemu);

    int type = blockIdx.y;
    const float* X = type == 0 ? x_a : x_b;
    const float* bias = type == 0 ? b_a : b_b;

    int t = threadIdx.x;
    for (int i = t; i < 512; i += 256) {
        int arr = i >> 7, col = i & 127;
        const float* p;
        if (type == 0)
            p = arr == 0 ? atA0 : arr == 1 ? atA1 : arr == 2 ? atA2 : atA3;
        else
            p = arr == 0 ? atB0 : arr == 1 ? atB1 : arr == 2 ? atB2 : atB3;
        satt[i] = __ldg(&p[col]);
    }

    int row0 = blockIdx.x * 128;
    const float4* X4 = (const float4*)X;
#pragma unroll
    for (int i = 0; i < 16; i++) {
        int idx = i * 256 + t;
        int r = idx >> 5, c4 = idx & 31;
        int gr = row0 + r;
        float4 v = make_float4(0.f, 0.f, 0.f, 0.f);
        if (gr < N) v = X4[(size_t)gr * 32 + c4];
        int base = r * 68 + c4 * 2;
        smemu[SW_AH + base] = pack_h2(v.x, v.y);
        smemu[SW_AH + base + 1] = pack_h2(v.z, v.w);
    }
    __syncthreads();

    float acc[64];
    gemm_compute1(sb, SW_AH, g_Wfrag[type], acc);

    uint32_t* Hout = g_h16[type];
    int rS0 = type == 0 ? 0 : 1, rS1 = type == 0 ? 2 : 3;
    int rD0 = type == 0 ? 1 : 0, rD1 = type == 0 ? 2 : 3;

    int wid = t >> 5, lane = t & 31;
    int wr = (wid >> 1) * 32, wc = (wid & 1) * 64;

    __syncthreads();  // done reading A smem; reuse as vbuf (pitch 134 floats)

#pragma unroll
    for (int rt = 0; rt < 2; rt++) {
#pragma unroll
        for (int hr = 0; hr < 2; hr++) {
            int lrow = wr + rt * 16 + hr * 8 + (lane >> 2);
            int grow = row0 + lrow;
#pragma unroll
            for (int nt = 0; nt < 8; nt++) {
                int col = wc + nt * 8 + (lane & 3) * 2;
                float2 bb = __ldg((const float2*)(bias + col));
                float v0 = acc[(rt * 8 + nt) * 4 + hr * 2] + bb.x;
                float v1 = acc[(rt * 8 + nt) * 4 + hr * 2 + 1] + bb.y;
                if (grow < N)
                    Hout[(size_t)grow * 64 + (col >> 1)] = pack_h2(v0, v1);
                *(float2*)(smemf + lrow * 134 + col) = make_float2(v0, v1);
            }
        }
    }
    __syncthreads();

    if (t < 128) {
        int node = row0 + t;
        if (node < N) {
            const float* vrow = smemf + t * 134;
            float* aS0 = &g_alphaS[rS0][0];
            float* aS1 = &g_alphaS[rS1][0];
            float* aD0 = &g_alphaD[rD0][0];
            float* aD1 = &g_alphaD[rD1][0];
#pragma unroll
            for (int h = 0; h < 8; h++) {
                float p0 = 0.f, p1 = 0.f, p2 = 0.f, p3 = 0.f;
#pragma unroll
                for (int i = 0; i < 16; i++) {
                    int col = h * 16 + i;
                    float v = vrow[col];
                    p0 = fmaf(v, satt[0 * 128 + col], p0);
                    p1 = fmaf(v, satt[1 * 128 + col], p1);
                    p2 = fmaf(v, satt[2 * 128 + col], p2);
                    p3 = fmaf(v, satt[3 * 128 + col], p3);
                }
                aS0[node * 8 + h] = p0;
                aS1[node * 8 + h] = p1;
                aD0[node * 8 + h] = p2;
                aD1[node * 8 + h] = p3;
            }
        }
    }
}

// ---------------- semantic score (blockIdx.y = rel), single-pass f16 ----------------
__global__ void __launch_bounds__(256, 2) sem_mma_kernel(
    const float* __restrict__ bk, const float* __restrict__ q) {
    extern __shared__ uint32_t smemu[];
    float* red = (float*)smemu + SEM_RED;
    uint32_t sb = smem_u32(smemu);
    int rel = blockIdx.y;
    int row0 = blockIdx.x * 128;

    stage_tile(sb, g_of[rel], row0, N);
    CP_COMMIT_WAIT();
    __syncthreads();

    float acc[64];
    gemm_compute1(sb, 0, g_Wfrag[2], acc);

    int t = threadIdx.x;
    int wid = t >> 5, lane = t & 31;
    int wr = (wid >> 1) * 32, wc = (wid & 1) * 64;

    float local = 0.f;
#pragma unroll
    for (int rt = 0; rt < 2; rt++) {
#pragma unroll
        for (int hr = 0; hr < 2; hr++) {
            int grow = row0 + wr + rt * 16 + hr * 8 + (lane >> 2);
            if (grow < N) {
#pragma unroll
                for (int nt = 0; nt < 8; nt++) {
                    int col = wc + nt * 8 + (lane & 3) * 2;
                    float2 bb = __ldg((const float2*)(bk + col));
                    float2 qq = __ldg((const float2*)(q + col));
                    float v0 = acc[(rt * 8 + nt) * 4 + hr * 2] + bb.x;
                    float v1 = acc[(rt * 8 + nt) * 4 + hr * 2 + 1] + bb.y;
                    local += tanhf(v0) * qq.x + tanhf(v1) * qq.y;
                }
            }
        }
    }
#pragma unroll
    for (int off = 16; off >= 1; off >>= 1)
        local += __shfl_down_sync(0xffffffff, local, off);
    __syncthreads();
    if (lane == 0) red[wid] = local;
    __syncthreads();
    if (t == 0) {
        float s = 0.f;
#pragma unroll
        for (int w = 0; w < 8; w++) s += red[w];
        atomicAdd(&g_score[rel], s);
    }
}

// ---------------- init ----------------
__global__ void init_kernel() {
    int i = blockIdx.x * blockDim.x + threadIdx.x;
    int stride = gridDim.x * blockDim.x;
    int* degf = &g_deg[0][0];
    for (int k = i; k < 4 * N; k += stride) degf[k] = 0;
    if (i < 4) g_score[i] = 0.f;
    if (i < 2 * 5 * HID) (&g_st[0][0][0])[i] = 0.f;
}

// ---------------- CSR build ----------------
__global__ void count_kernel(const int* __restrict__ e0, const int* __restrict__ e1,
                             const int* __restrict__ e2, const int* __restrict__ e3) {
    int rel = blockIdx.y;
    const int* ei = rel == 0 ? e0 : rel == 1 ? e1 : rel == 2 ? e2 : e3;
    int e = blockIdx.x * blockDim.x + threadIdx.x;
    if (e < E) atomicAdd(&g_deg[rel][ei[E + e]], 1);
}

__global__ void scan1_kernel() {
    int rel = blockIdx.y;
    int i = blockIdx.x * 1024 + threadIdx.x;
    int lane = threadIdx.x & 31, wid = threadIdx.x >> 5;
    int v = (i < N) ? g_deg[rel][i] : 0;
    int x = v;
#pragma unroll
    for (int o = 1; o < 32; o <<= 1) {
        int y = __shfl_up_sync(0xffffffff, x, o);
        if (lane >= o) x += y;
    }
    __shared__ int ws[32];
    if (lane == 31) ws[wid] = x;
    __syncthreads();
    if (wid == 0) {
        int s = ws[lane];
#pragma unroll
        for (int o = 1; o < 32; o <<= 1) {
            int y = __shfl_up_sync(0xffffffff, s, o);
            if (lane >= o) s += y;
        }
        ws[lane] = s;
    }
    __syncthreads();
    int incl = x + (wid ? ws[wid - 1] : 0);
    if (i < N) g_rowptr[rel][i] = incl - v;
    if (threadIdx.x == 1023) g_bsum[rel][blockIdx.x] = incl;
}

__global__ void scan2_kernel() {
    int rel = blockIdx.x;
    int t = threadIdx.x;  // 128
    int lane = t & 31, wid = t >> 5;
    int v = (t < 98) ? g_bsum[rel][t] : 0;
    int x = v;
#pragma unroll
    for (int o = 1; o < 32; o <<= 1) {
        int y = __shfl_up_sync(0xffffffff, x, o);
        if (lane >= o) x += y;
    }
    __shared__ int ws[4];
    if (lane == 31) ws[wid] = x;
    __syncthreads();
    int prefix = 0;
    for (int k = 0; k < wid; k++) prefix += ws[k];
    int incl = x + prefix;
    if (t < 98) g_boff[rel][t] = incl - v;
    if (t == 0) g_rowptr[rel][N] = E;
}

__global__ void scan3_kernel() {
    int rel = blockIdx.y;
    int i = blockIdx.x * 1024 + threadIdx.x;
    if (i < N) {
        g_rowptr[rel][i] += g_boff[rel][blockIdx.x];
        g_deg[rel][i] = 0;  // reset cursor for scatter
    }
}

__global__ void scatter_kernel(const int* __restrict__ e0, const int* __restrict__ e1,
                               const int* __restrict__ e2, const int* __restrict__ e3) {
    int rel = blockIdx.y;
    const int* ei = rel == 0 ? e0 : rel == 1 ? e1 : rel == 2 ? e2 : e3;
    int e = blockIdx.x * blockDim.x + threadIdx.x;
    if (e < E) {
        int s = ei[e], d = ei[E + e];
        int pos = g_rowptr[rel][d] + atomicAdd(&g_deg[rel][d], 1);
        g_srcs[rel][pos] = s;
    }
}

// ---------------- aggregate: TWO nodes per warp (16 lanes x 8 dims each) ----------------
__global__ void aggregate_kernel() {
    int rel = blockIdx.y;
    const uint32_t* hs = g_h16[(rel == 0 || rel == 2) ? 0 : 1];
    int w = (blockIdx.x * blockDim.x + threadIdx.x) >> 5;
    int lane = threadIdx.x & 31;
    int n = w * 2 + (lane >> 4);
    if (n >= N) return;
    int sl = lane & 15;       // sublane: dims [sl*8, sl*8+8)
    int h = sl >> 1;

    const float* aS = g_alphaS[rel];
    float ad = g_alphaD[rel][n * 8 + h];
    int beg = g_rowptr[rel][n], end = g_rowptr[rel][n + 1];
    const int* srcs = g_srcs[rel];

    float den = 0.f;
    float a0v[8];
#pragma unroll
    for (int i = 0; i < 8; i++) a0v[i] = 0.f;

    int e = beg;
    for (; e + 2 <= end; e += 2) {
        int s0 = srcs[e], s1 = srcs[e + 1];
        float a0 = aS[s0 * 8 + h] + ad;
        float a1 = aS[s1 * 8 + h] + ad;
        a0 = a0 > 0.f ? a0 : 0.2f * a0;
        a1 = a1 > 0.f ? a1 : 0.2f * a1;
        float w0 = __expf(a0), w1 = __expf(a1);
        den += w0 + w1;
        uint4 u0 = *reinterpret_cast<const uint4*>(hs + (size_t)s0 * 64 + sl * 4);
        uint4 u1 = *reinterpret_cast<const uint4*>(hs + (size_t)s1 * 64 + sl * 4);
        float f[8], g[8];
        unpack_h2(u0.x, f[0], f[1]); unpack_h2(u0.y, f[2], f[3]);
        unpack_h2(u0.z, f[4], f[5]); unpack_h2(u0.w, f[6], f[7]);
        unpack_h2(u1.x, g[0], g[1]); unpack_h2(u1.y, g[2], g[3]);
        unpack_h2(u1.z, g[4], g[5]); unpack_h2(u1.w, g[6], g[7]);
#pragma unroll
        for (int i = 0; i < 8; i++)
            a0v[i] = fmaf(w0, f[i], fmaf(w1, g[i], a0v[i]));
    }
    if (e < end) {
        int s0 = srcs[e];
        float a0 = aS[s0 * 8 + h] + ad;
        a0 = a0 > 0.f ? a0 : 0.2f * a0;
        float w0 = __expf(a0);
        den += w0;
        uint4 u0 = *reinterpret_cast<const uint4*>(hs + (size_t)s0 * 64 + sl * 4);
        float f[8];
        unpack_h2(u0.x, f[0], f[1]); unpack_h2(u0.y, f[2], f[3]);
        unpack_h2(u0.z, f[4], f[5]); unpack_h2(u0.w, f[6], f[7]);
#pragma unroll
        for (int i = 0; i < 8; i++)
            a0v[i] = fmaf(w0, f[i], a0v[i]);
    }
    float inv = 1.f / (den + 1e-16f);
    uint4 o;
    o.x = pack_h2(fmaxf(a0v[0] * inv, 0.f), fmaxf(a0v[1] * inv, 0.f));
    o.y = pack_h2(fmaxf(a0v[2] * inv, 0.f), fmaxf(a0v[3] * inv, 0.f));
    o.z = pack_h2(fmaxf(a0v[4] * inv, 0.f), fmaxf(a0v[5] * inv, 0.f));
    o.w = pack_h2(fmaxf(a0v[6] * inv, 0.f), fmaxf(a0v[7] * inv, 0.f));
    *reinterpret_cast<uint4*>(&g_of[rel][(size_t)n * 64 + sl * 4]) = o;
}

// ---------------- BN stats from fp16 o (5 stats per type per column) ----------------
__global__ void stats_kernel() {
    int type = blockIdx.y;
    int rel0 = type == 0 ? 1 : 0;
    int rel1 = type == 0 ? 2 : 3;
    int t = threadIdx.x;        // 256
    int cp = t & 63, rg = t >> 6;
    int r0 = blockIdx.x * 512;
    int rend = r0 + 512;
    if (rend > N) rend = N;

    float s0a = 0.f, s1a = 0.f, ss0a = 0.f, ss1a = 0.f, cxa = 0.f;
    float s0b = 0.f, s1b = 0.f, ss0b = 0.f, ss1b = 0.f, cxb = 0.f;
    for (int r = r0 + rg; r < rend; r += 4) {
        uint32_t u0 = g_of[rel0][(size_t)r * 64 + cp];
        uint32_t u1 = g_of[rel1][(size_t)r * 64 + cp];
        float xa, xb, ya, yb;
        unpack_h2(u0, xa, xb);
        unpack_h2(u1, ya, yb);
        s0a += xa; s1a += ya; ss0a += xa * xa; ss1a += ya * ya; cxa += xa * ya;
        s0b += xb; s1b += yb; ss0b += xb * xb; ss1b += yb * yb; cxb += xb * yb;
    }
    __shared__ float red[4][64][10];
    float* my = red[rg][cp];
    my[0] = s0a; my[1] = s1a; my[2] = ss0a; my[3] = ss1a; my[4] = cxa;
    my[5] = s0b; my[6] = s1b; my[7] = ss0b; my[8] = ss1b; my[9] = cxb;
    __syncthreads();
    if (rg == 0) {
#pragma unroll
        for (int k = 0; k < 10; k++) {
            float v = red[0][cp][k] + red[1][cp][k] + red[2][cp][k] + red[3][cp][k];
            int stat = k % 5;
            int col = cp * 2 + (k / 5);
            atomicAdd(&g_st[type][stat][col], v);
        }
    }
}

// ---------------- BN params (computes semantic attn inline) ----------------
__global__ void bnparam_kernel(const float* __restrict__ gamma,
                               const float* __restrict__ beta) {
    int t = threadIdx.x;  // 256
    int type = t >> 7, j = t & 127;
    int r0 = type == 0 ? 1 : 0, r1 = type == 0 ? 2 : 3;
    float sc0 = g_score[r0] / (float)N, sc1 = g_score[r1] / (float)N;
    float m = fmaxf(sc0, sc1);
    float e0 = expf(sc0 - m), e1 = expf(sc1 - m);
    float a0 = e0 / (e0 + e1), a1 = e1 / (e0 + e1);
    if (j == 0) {
        g_attn[type * 2 + 0] = a0;
        g_attn[type * 2 + 1] = a1;
    }
    float s0 = g_st[type][0][j], s1 = g_st[type][1][j];
    float ss0 = g_st[type][2][j], ss1 = g_st[type][3][j], cx = g_st[type][4][j];
    float mu = (a0 * s0 + a1 * s1) / (float)N;
    float ex2 = (a0 * a0 * ss0 + 2.f * a0 * a1 * cx + a1 * a1 * ss1) / (float)N;
    float var = ex2 - mu * mu;
    float rstd = rsqrtf(var + 1e-5f);
    float sc = rstd * gamma[j];
    g_scale[type][j] = sc;
    g_shift[type][j] = beta[j] - mu * sc;
}

// ---------------- fused combine + normalize (reads fp16 o) ----------------
__global__ void combine_norm_kernel(float* __restrict__ out) {
    int stride = gridDim.x * blockDim.x;
    int total = 2 * N * 32;  // uint2 (4 cols) units
    for (int i = blockIdx.x * blockDim.x + threadIdx.x; i < total; i += stride) {
        int type = (i >= N * 32) ? 1 : 0;
        int local = i - type * N * 32;
        const uint2* o0 = (const uint2*)(type == 0 ? g_of[1] : g_of[0]);
        const uint2* o1 = (const uint2*)(type == 0 ? g_of[2] : g_of[3]);
        float a0 = g_attn[type * 2 + 0], a1 = g_attn[type * 2 + 1];
        uint2 u0 = o0[local], u1 = o1[local];
        float x0, x1, x2, x3, y0, y1, y2, y3;
        unpack_h2(u0.x, x0, x1);
        unpack_h2(u0.y, x2, x3);
        unpack_h2(u1.x, y0, y1);
        unpack_h2(u1.y, y2, y3);
        int j = (local & 31) * 4;
        const float* sc = g_scale[type];
        const float* sf = g_shift[type];
        float4 r;
        r.x = (a0 * x0 + a1 * y0) * sc[j + 0] + sf[j + 0];
        r.y = (a0 * x1 + a1 * y1) * sc[j + 1] + sf[j + 1];
        r.z = (a0 * x2 + a1 * y2) * sc[j + 2] + sf[j + 2];
        r.w = (a0 * x3 + a1 * y3) * sc[j + 3] + sf[j + 3];
        ((float4*)out)[i] = r;
    }
}

// ---------------- host ----------------
static cudaStream_t g_s2 = 0;
static cudaEvent_t g_evA, g_evB, g_evC, g_evD;

extern "C" void kernel_launch(void* const* d_in, const int* in_sizes, int n_in,
                              void* d_out, int out_size) {
    const float* x_a = (const float*)d_in[0];
    const float* x_b = (const float*)d_in[1];
    const int* ei_ab = (const int*)d_in[2];
    const int* ei_ba = (const int*)d_in[3];
    const int* ei_aa = (const int*)d_in[4];
    const int* ei_bb = (const int*)d_in[5];
    const float* W_a = (const float*)d_in[6];
    const float* b_a = (const float*)d_in[7];
    const float* W_b = (const float*)d_in[8];
    const float* b_b = (const float*)d_in[9];
    const float* att_ab_s = (const float*)d_in[10];
    const float* att_ab_d = (const float*)d_in[11];
    const float* att_ba_s = (const float*)d_in[12];
    const float* att_ba_d = (const float*)d_in[13];
    const float* att_aa_s = (const float*)d_in[14];
    const float* att_aa_d = (const float*)d_in[15];
    const float* att_bb_s = (const float*)d_in[16];
    const float* att_bb_d = (const float*)d_in[17];
    const float* Wk = (const float*)d_in[18];
    const float* bk = (const float*)d_in[19];
    const float* q  = (const float*)d_in[20];
    const float* gamma = (const float*)d_in[21];
    const float* beta  = (const float*)d_in[22];
    float* out = (float*)d_out;

    if (g_s2 == 0) {
        cudaStreamCreateWithFlags(&g_s2, cudaStreamNonBlocking);
        cudaEventCreateWithFlags(&g_evA, cudaEventDisableTiming);
        cudaEventCreateWithFlags(&g_evB, cudaEventDisableTiming);
        cudaEventCreateWithFlags(&g_evC, cudaEventDisableTiming);
        cudaEventCreateWithFlags(&g_evD, cudaEventDisableTiming);
        cudaFuncSetAttribute(proj_mma_kernel, cudaFuncAttributeMaxDynamicSharedMemorySize, PROJ_SMEM_BYTES);
        cudaFuncSetAttribute(sem_mma_kernel, cudaFuncAttributeMaxDynamicSharedMemorySize, SEM_SMEM_BYTES);
    }

    init_kernel<<<512, 256>>>();

    // fork: CSR chain on side stream, overlapped with projection GEMMs
    cudaEventRecord(g_evA, 0);
    cudaStreamWaitEvent(g_s2, g_evA, 0);

    prep_w_kernel<<<3, 256>>>(W_a, W_b, Wk);

    int mmGrid = (N + 127) / 128;  // 782
    dim3 pGrid(mmGrid, 2);
    proj_mma_kernel<<<pGrid, 256, PROJ_SMEM_BYTES>>>(
        x_a, x_b, b_a, b_b,
        att_ab_s, att_aa_s, att_ba_d, att_aa_d,
        att_ba_s, att_bb_s, att_ab_d, att_bb_d);

    dim3 eGrid((E + 255) / 256, 4);
    dim3 sGrid((N + 1023) / 1024, 4);
    count_kernel<<<eGrid, 256, 0, g_s2>>>(ei_ab, ei_ba, ei_aa, ei_bb);
    scan1_kernel<<<sGrid, 1024, 0, g_s2>>>();
    scan2_kernel<<<4, 128, 0, g_s2>>>();
    scan3_kernel<<<sGrid, 1024, 0, g_s2>>>();
    scatter_kernel<<<eGrid, 256, 0, g_s2>>>(ei_ab, ei_ba, ei_aa, ei_bb);

    // join: aggregate needs alphas (stream 0) + CSR (s2)
    cudaEventRecord(g_evB, g_s2);
    cudaStreamWaitEvent(0, g_evB, 0);

    dim3 aggGrid(((N + 1) / 2 * 32 + 255) / 256, 4);
    aggregate_kernel<<<aggGrid, 256>>>();

    // fork: stats on side stream, overlapped with semantic GEMMs
    cudaEventRecord(g_evC, 0);
    cudaStreamWaitEvent(g_s2, g_evC, 0);

    dim3 semGrid(mmGrid, 4);
    sem_mma_kernel<<<semGrid, 256, SEM_SMEM_BYTES>>>(bk, q);

    dim3 stGrid2((N + 511) / 512, 2);
    stats_kernel<<<stGrid2, 256, 0, g_s2>>>();

    // join: bnparam needs stats (s2) + scores (stream 0)
    cudaEventRecord(g_evD, g_s2);
    cudaStreamWaitEvent(0, g_evD, 0);

    bnparam_kernel<<<1, 256>>>(gamma, beta);

    combine_norm_kernel<<<4096, 256>>>(out);
}